// round 11
// baseline (speedup 1.0000x reference)
#include <cuda_runtime.h>
#include <math.h>

#define NSIZE 96
#define MTOT  (NSIZE * NSIZE)        // 9216
#define GDIM  (2 * NSIZE - 1)        // 191
#define GTOT  (GDIM * GDIM)          // 36481
#define CHUNKS 32
#define CROWS  (NSIZE / CHUNKS)      // 3 source rows per chunk
#define AJT    4                     // aj values per block (one per warp)
#define GROWS  (CROWS + AJT - 1)     // 6 staged G rows
#define NBLOCKS (24 * CHUNKS)        // 768
#define NTHREADS 128

// Physics constants (match reference)
#define WAVELEN 1.55e-6
#define DZ      1.0e-5
#define TWO_PI  6.283185307179586476925286766559
#define TWO_PI_F 6.2831853071795864769f
// (dz/lambda)^2 in extended precision
#define AZ2_F  41.62330905306972f

typedef unsigned long long ull;

// packed f32x2 fma: d = a*b + c (elementwise, 2 packed floats per reg pair)
#define FFMA2(d, a, b, c) \
    asm("fma.rn.f32x2 %0, %1, %2, %3;" : "=l"(d) : "l"(a), "l"(b), "l"(c))
#define UNPACK2(lo, hi, s) \
    asm("mov.b64 {%0, %1}, %2;" : "=f"(lo), "=f"(hi) : "l"(s))

// Scratch in __device__ globals (no allocations allowed)
__device__ float4 d_modes4[MTOT];    // (mx, mx, my, my) pre-duplicated
__device__ float2 d_G[GTOT];
__device__ float  d_part_re[CHUNKS * MTOT];
__device__ float  d_part_im[CHUNKS * MTOT];
__device__ unsigned g_ctr[2];        // monotonic barrier tickets (never reset)

// Grid-wide barrier, replay-safe: tickets are monotonic across launches.
__device__ __forceinline__ void grid_barrier(int i) {
    __syncthreads();
    if (threadIdx.x == 0) {
        __threadfence();
        unsigned ticket = atomicAdd(&g_ctr[i], 1u) + 1u;
        unsigned target = ((ticket + NBLOCKS - 1u) / NBLOCKS) * NBLOCKS;
        while (*(volatile unsigned*)&g_ctr[i] < target) { }
        __threadfence();
    }
    __syncthreads();
}

__global__ void __launch_bounds__(NTHREADS, 6)
fused_all(const float* __restrict__ x,
          const float* __restrict__ w,
          const float* __restrict__ xc,
          const float* __restrict__ yc,
          float* __restrict__ out, int out_size) {
    __shared__ __align__(16) float4 sm4[CROWS * NSIZE];  // modes (3x96, dup)
    __shared__ __align__(16) float2 sg[GROWS * GDIM];    // G window (6x191)

    int tid = threadIdx.x;
    int bx  = blockIdx.x;

    // ---------------- Phase A: prep (all fp32) ---------------------------
    {
        int i = bx * NTHREADS + tid;
        if (i < MTOT) {
            float s, c;
            sincosf(w[i], &s, &c);
            float xv = x[i];
            float mr = xv * c, mi = xv * s;
            d_modes4[i] = make_float4(mr, mr, mi, mi);
        } else if (i < 2 * MTOT) {
            int t = i - MTOT;
            int da = t / NSIZE;
            int db = t - da * NSIZE;

            const float inv_lam = (float)(1.0 / WAVELEN);
            float ax = (xc[da] - xc[0]) * inv_lam;
            float ay = (yc[db] - yc[0]) * inv_lam;
            float q  = fmaf(ax, ax, fmaf(ay, ay, AZ2_F));  // (r/lambda)^2

            // frac(sqrt(q)) with FMA-cancellation Newton refinement
            float s0 = sqrtf(q);
            float e  = fmaf(-s0, s0, q);
            float ds = e / (2.0f * s0);
            float frac = (s0 - truncf(s0)) + ds;
            float sn, cs;
            sincosf(TWO_PI_F * frac, &sn, &cs);

            float r2f  = q * (float)(WAVELEN * WAVELEN);
            float invr = rsqrtf(r2f);
            float inv_r2 = invr * invr;
            const float dAf = (float)(1.55e-6 * 1.55e-6);
            float ar = (float)(DZ / TWO_PI) * inv_r2 * invr;
            float ai = (float)(-DZ / WAVELEN) * inv_r2;
            float2 g = make_float2((ar * cs - ai * sn) * dAf,
                                   (ar * sn + ai * cs) * dAf);

            int rp = (NSIZE - 1) + da, rm = (NSIZE - 1) - da;
            int cp = (NSIZE - 1) + db, cm = (NSIZE - 1) - db;
            d_G[rp * GDIM + cp] = g;
            d_G[rp * GDIM + cm] = g;
            d_G[rm * GDIM + cp] = g;
            d_G[rm * GDIM + cm] = g;
        }
    }

    grid_barrier(0);

    // ---------------- Phase B: correlation, deferred-combine FFMA2 -------
    // Per cMAC: accA += (mx,mx)*(gx,gy); accB += (my,my)*(gx,gy)
    // re = accA.lo - accB.hi ; im = accA.hi + accB.lo  (combined once).
    {
        int ajb = bx % (NSIZE / AJT);        // 0..23
        int ch  = bx / (NSIZE / AJT);        // 0..31
        int aj0 = ajb * AJT;
        int ai0 = ch * CROWS;

        for (int t = tid; t < CROWS * NSIZE; t += NTHREADS)
            sm4[t] = d_modes4[ai0 * NSIZE + t];

        int row0 = ai0 - aj0 + (NSIZE - 1) - (AJT - 1);
        for (int t = tid; t < GROWS * GDIM; t += NTHREADS) {
            int ci = t / GDIM;
            int cc = t - ci * GDIM;
            sg[t] = d_G[(row0 + ci) * GDIM + cc];
        }
        __syncthreads();

        int ww   = tid >> 5;
        int lane = tid & 31;
        int bj0  = lane * 3;

        ull a0A = 0, a0B = 0, a1A = 0, a1B = 0, a2A = 0, a2B = 0;

        #pragma unroll
        for (int ci = 0; ci < CROWS; ci++) {
            const ulonglong2* __restrict__ mrow =
                (const ulonglong2*)&sm4[ci * NSIZE];
            const ull* __restrict__ grow =
                (const ull*)&sg[(ci + (AJT - 1) - ww) * GDIM + (NSIZE - 1) - bj0];
            ull gm1 = grow[-1];
            ull gm2 = grow[-2];
            #pragma unroll 8
            for (int bi = 0; bi < NSIZE; bi++) {
                ull g0 = grow[bi];               // (gx, gy), lane-contiguous
                ulonglong2 mm = mrow[bi];        // broadcast: (mx,mx),(my,my)
                FFMA2(a0A, mm.x, g0,  a0A);
                FFMA2(a0B, mm.y, g0,  a0B);
                FFMA2(a1A, mm.x, gm1, a1A);
                FFMA2(a1B, mm.y, gm1, a1B);
                FFMA2(a2A, mm.x, gm2, a2A);
                FFMA2(a2B, mm.y, gm2, a2B);
                gm2 = gm1; gm1 = g0;             // slide (register rename)
            }
        }

        float alo, ahi, blo, bhi;
        int base = ch * MTOT + (aj0 + ww) * NSIZE + bj0;
        UNPACK2(alo, ahi, a0A); UNPACK2(blo, bhi, a0B);
        d_part_re[base]     = alo - bhi;  d_part_im[base]     = ahi + blo;
        UNPACK2(alo, ahi, a1A); UNPACK2(blo, bhi, a1B);
        d_part_re[base + 1] = alo - bhi;  d_part_im[base + 1] = ahi + blo;
        UNPACK2(alo, ahi, a2A); UNPACK2(blo, bhi, a2B);
        d_part_re[base + 2] = alo - bhi;  d_part_im[base + 2] = ahi + blo;
    }

    grid_barrier(1);

    // ---------------- Phase C: reduce + format ---------------------------
    {
        int t = bx * NTHREADS + tid;
        if (out_size == 2 * MTOT) {
            if (t < 2 * MTOT) {
                const float* __restrict__ src =
                    (t < MTOT) ? d_part_re : d_part_im;
                int j = (t < MTOT) ? t : t - MTOT;
                float acc = 0.f;
                #pragma unroll
                for (int ch = 0; ch < CHUNKS; ch++)
                    acc += src[ch * MTOT + j];
                out[t] = acc;
            }
        } else if (out_size == MTOT) {
            if (t < MTOT) {
                float acc = 0.f;
                #pragma unroll
                for (int ch = 0; ch < CHUNKS; ch++)
                    acc += d_part_re[ch * MTOT + t];
                out[t] = acc;
            }
        } else {
            if (t < MTOT) {
                float re = 0.f, im = 0.f;
                #pragma unroll
                for (int ch = 0; ch < CHUNKS; ch++) {
                    re += d_part_re[ch * MTOT + t];
                    im += d_part_im[ch * MTOT + t];
                }
                ((float2*)out)[t] = make_float2(re, im);
            }
        }
    }
}

extern "C" void kernel_launch(void* const* d_in, const int* in_sizes, int n_in,
                              void* d_out, int out_size) {
    const float* x  = (const float*)d_in[0];
    const float* w  = (const float*)d_in[1];
    const float* xc = (const float*)d_in[2];
    const float* yc = (const float*)d_in[3];

    fused_all<<<NBLOCKS, NTHREADS>>>(x, w, xc, yc, (float*)d_out, out_size);
}